// round 4
// baseline (speedup 1.0000x reference)
#include <cuda_runtime.h>

// ---------------------------------------------------------------------------
// FSRGraphConv, atomic-free aggregation:
//   counting-sort edges by dst -> warp-per-dst register aggregation ->
//   feat_mean stored directly -> fused 50000x288x128 fp32 GEMM (f32x2).
// ---------------------------------------------------------------------------

#define IN_F   128
#define E_F    32
#define FEAT   160
#define OUT_F  128
#define MAX_NODES 50000
#define MAX_EDGES 800000

__device__ __align__(16) float g_acc[(size_t)MAX_NODES * FEAT];   // feat_mean, 32 MB
__device__ int  g_cnt[MAX_NODES];
__device__ int  g_off[MAX_NODES + 1];
__device__ int  g_cur[MAX_NODES];
__device__ __align__(8) int2 g_pairs[MAX_EDGES];                  // (src, eid) sorted by dst
__device__ __align__(16) float g_Wc[FEAT * OUT_F];
__device__ __align__(16) float g_W1t[IN_F * OUT_F];

// ---------------------------------------------------------------------------
__global__ void zero_cnt_kernel(int n_nodes) {
    int i = blockIdx.x * blockDim.x + threadIdx.x;
    if (i < n_nodes) g_cnt[i] = 0;
}

__global__ void hist_kernel(const int* __restrict__ dst_idx, int n_edges) {
    int i = blockIdx.x * blockDim.x + threadIdx.x;
    if (i < n_edges) atomicAdd(&g_cnt[dst_idx[i]], 1);
}

// single block, 1024 threads: exclusive scan of g_cnt into g_off (+ g_cur copy)
__global__ void scan_kernel(int n_nodes) {
    __shared__ int ss[1024];
    int t = threadIdx.x;
    int run = (n_nodes + 1023) >> 10;
    int base = t * run;

    // pass 1: per-thread sum
    int s = 0;
    for (int i = 0; i < run; i++) {
        int idx = base + i;
        if (idx < n_nodes) s += g_cnt[idx];
    }
    ss[t] = s;
    __syncthreads();
    // Hillis-Steele inclusive scan
    for (int off = 1; off < 1024; off <<= 1) {
        int v = (t >= off) ? ss[t - off] : 0;
        __syncthreads();
        ss[t] += v;
        __syncthreads();
    }
    int tbase = (t > 0) ? ss[t - 1] : 0;
    // pass 2: write exclusive offsets
    int acc = tbase;
    for (int i = 0; i < run; i++) {
        int idx = base + i;
        if (idx < n_nodes) {
            g_off[idx] = acc;
            g_cur[idx] = acc;
            acc += g_cnt[idx];
        }
    }
    if (t == 1023) g_off[n_nodes] = ss[1023];
}

__global__ void bucket_kernel(const int* __restrict__ src_idx,
                              const int* __restrict__ dst_idx,
                              int n_edges) {
    int e = blockIdx.x * blockDim.x + threadIdx.x;
    if (e < n_edges) {
        int d = dst_idx[e];
        int pos = atomicAdd(&g_cur[d], 1);
        g_pairs[pos] = make_int2(src_idx[e], e);
    }
}

// one warp per dst node; lanes cover 160 feats (float4 of h + 1 float of eftr)
__global__ void aggregate_kernel(const float* __restrict__ h,
                                 const float* __restrict__ eftr,
                                 int n_nodes) {
    int lane = threadIdx.x & 31;
    int w    = (blockIdx.x * blockDim.x + threadIdx.x) >> 5;
    if (w >= n_nodes) return;

    int start = g_off[w];
    int end   = g_off[w + 1];

    float4 ah = make_float4(0.f, 0.f, 0.f, 0.f);
    float  ae = 0.f;

    int2 p = (start < end) ? g_pairs[start] : make_int2(0, 0);
    for (int j = start; j < end; j++) {
        int2 cur = p;
        if (j + 1 < end) p = g_pairs[j + 1];
        float4 hv = reinterpret_cast<const float4*>(h + (size_t)cur.x * IN_F)[lane];
        float  ev = eftr[(size_t)cur.y * E_F + lane];
        ah.x += hv.x; ah.y += hv.y; ah.z += hv.z; ah.w += hv.w;
        ae += ev;
    }
    float inv = 1.f / (float)max(end - start, 1);
    ah.x *= inv; ah.y *= inv; ah.z *= inv; ah.w *= inv;
    ae *= inv;

    float* arow = g_acc + (size_t)w * FEAT;
    reinterpret_cast<float4*>(arow)[lane] = ah;
    arow[IN_F + lane] = ae;
}

// ---------------------------------------------------------------------------
__global__ void prep_wc_kernel(const float* __restrict__ weight,
                               const float* __restrict__ W_w) {
    __shared__ float wrow[OUT_F];
    int k = blockIdx.x;
    int o = threadIdx.x;
    wrow[o] = weight[k * OUT_F + o];
    __syncthreads();
    const float* wr = W_w + (size_t)o * (IN_F + OUT_F) + IN_F;
    float s = 0.f;
#pragma unroll 4
    for (int c = 0; c < OUT_F; c++) s = fmaf(wrow[c], wr[c], s);
    g_Wc[k * OUT_F + o] = s;
}

__global__ void prep_w1t_kernel(const float* __restrict__ W_w) {
    int idx = blockIdx.x * blockDim.x + threadIdx.x;
    if (idx < IN_F * OUT_F) {
        int k = idx >> 7;
        int o = idx & 127;
        g_W1t[idx] = W_w[(size_t)o * (IN_F + OUT_F) + k];
    }
}

// ---------------------------------------------------------------------------
// packed fp32x2 helpers
__device__ __forceinline__ unsigned long long ffma2(unsigned long long a,
                                                    unsigned long long b,
                                                    unsigned long long c) {
    unsigned long long d;
    asm("fma.rn.f32x2 %0, %1, %2, %3;" : "=l"(d) : "l"(a), "l"(b), "l"(c));
    return d;
}
__device__ __forceinline__ unsigned long long pack2(float lo, float hi) {
    unsigned long long d;
    asm("mov.b64 %0, {%1, %2};" : "=l"(d) : "f"(lo), "f"(hi));
    return d;
}
__device__ __forceinline__ float2 unpack2(unsigned long long v) {
    float lo, hi;
    asm("mov.b64 {%0, %1}, %2;" : "=f"(lo), "=f"(hi) : "l"(v));
    return make_float2(lo, hi);
}

// fused GEMM: out = [h_dst | feat_mean] @ [W1t; Wc] + (W_b + bias)
#define BM 128
#define BN 128
#define BK 16

__global__ void gemm_kernel(const float* __restrict__ h,
                            const float* __restrict__ W_b,
                            const float* __restrict__ bias,
                            float* __restrict__ out,
                            int n_nodes) {
    __shared__ float Xs[BK][BM + 4];
    __shared__ __align__(16) float Ws[BK][BN];

    int m0 = blockIdx.x * BM;
    int t  = threadIdx.x;
    int tx = t & 15;
    int ty = t >> 4;

    unsigned long long acc2[8][4];
#pragma unroll
    for (int i = 0; i < 8; i++)
#pragma unroll
        for (int j = 0; j < 4; j++) acc2[i][j] = 0ull;

    for (int kc = 0; kc < 18; kc++) {
        // --- X tile (128 x 16), stored k-major ---
#pragma unroll
        for (int i = 0; i < 2; i++) {
            int idx = t + i * 256;
            int m   = idx >> 2;
            int k4  = idx & 3;
            int node = m0 + m;
            float4 v = make_float4(0.f, 0.f, 0.f, 0.f);
            if (node < n_nodes) {
                if (kc < 8) {
                    v = *reinterpret_cast<const float4*>(
                            h + (size_t)node * IN_F + kc * BK + k4 * 4);
                } else {
                    v = *reinterpret_cast<const float4*>(
                            g_acc + (size_t)node * FEAT + (kc - 8) * BK + k4 * 4);
                }
            }
            Xs[k4 * 4 + 0][m] = v.x;
            Xs[k4 * 4 + 1][m] = v.y;
            Xs[k4 * 4 + 2][m] = v.z;
            Xs[k4 * 4 + 3][m] = v.w;
        }
        // --- W tile (16 x 128) ---
        const float* Wsrc = (kc < 8) ? (g_W1t + kc * BK * OUT_F)
                                     : (g_Wc + (kc - 8) * BK * OUT_F);
#pragma unroll
        for (int i = 0; i < 2; i++) {
            int idx = t + i * 256;
            int k   = idx >> 5;
            int n4  = idx & 31;
            *reinterpret_cast<float4*>(&Ws[k][n4 * 4]) =
                *reinterpret_cast<const float4*>(Wsrc + k * OUT_F + n4 * 4);
        }
        __syncthreads();

#pragma unroll
        for (int kk = 0; kk < BK; kk++) {
            float4 x0 = *reinterpret_cast<const float4*>(&Xs[kk][ty * 8]);
            float4 x1 = *reinterpret_cast<const float4*>(&Xs[kk][ty * 8 + 4]);
            const unsigned long long* wrow =
                reinterpret_cast<const unsigned long long*>(&Ws[kk][tx * 8]);
            unsigned long long w01 = wrow[0];
            unsigned long long w23 = wrow[1];
            unsigned long long w45 = wrow[2];
            unsigned long long w67 = wrow[3];

            float xv[8] = {x0.x, x0.y, x0.z, x0.w, x1.x, x1.y, x1.z, x1.w};
#pragma unroll
            for (int i = 0; i < 8; i++) {
                unsigned long long xx = pack2(xv[i], xv[i]);
                acc2[i][0] = ffma2(xx, w01, acc2[i][0]);
                acc2[i][1] = ffma2(xx, w23, acc2[i][1]);
                acc2[i][2] = ffma2(xx, w45, acc2[i][2]);
                acc2[i][3] = ffma2(xx, w67, acc2[i][3]);
            }
        }
        __syncthreads();
    }

    float bv[8];
#pragma unroll
    for (int j = 0; j < 8; j++) {
        int o = tx * 8 + j;
        bv[j] = W_b[o] + bias[o];
    }
#pragma unroll
    for (int i = 0; i < 8; i++) {
        int node = m0 + ty * 8 + i;
        if (node < n_nodes) {
            float* orow = out + (size_t)node * OUT_F + tx * 8;
            float2 a01 = unpack2(acc2[i][0]);
            float2 a23 = unpack2(acc2[i][1]);
            float2 a45 = unpack2(acc2[i][2]);
            float2 a67 = unpack2(acc2[i][3]);
            float4 r0 = make_float4(a01.x + bv[0], a01.y + bv[1],
                                    a23.x + bv[2], a23.y + bv[3]);
            float4 r1 = make_float4(a45.x + bv[4], a45.y + bv[5],
                                    a67.x + bv[6], a67.y + bv[7]);
            *reinterpret_cast<float4*>(orow)     = r0;
            *reinterpret_cast<float4*>(orow + 4) = r1;
        }
    }
}

// ---------------------------------------------------------------------------
extern "C" void kernel_launch(void* const* d_in, const int* in_sizes, int n_in,
                              void* d_out, int out_size) {
    const float* h      = (const float*)d_in[0];
    const float* eftr   = (const float*)d_in[1];
    const float* weight = (const float*)d_in[2];
    const float* W_w    = (const float*)d_in[3];
    const float* W_b    = (const float*)d_in[4];
    const float* bias   = (const float*)d_in[5];
    const int*   src    = (const int*)d_in[6];
    const int*   dst    = (const int*)d_in[7];
    float* out = (float*)d_out;

    int n_nodes = in_sizes[0] / IN_F;
    int n_edges = in_sizes[7];

    zero_cnt_kernel<<<(n_nodes + 255) / 256, 256>>>(n_nodes);
    prep_wc_kernel<<<FEAT, OUT_F>>>(weight, W_w);
    prep_w1t_kernel<<<(IN_F * OUT_F + 255) / 256, 256>>>(W_w);
    hist_kernel<<<(n_edges + 255) / 256, 256>>>(dst, n_edges);
    scan_kernel<<<1, 1024>>>(n_nodes);
    bucket_kernel<<<(n_edges + 255) / 256, 256>>>(src, dst, n_edges);
    aggregate_kernel<<<(n_nodes + 7) / 8, 256>>>(h, eftr, n_nodes);
    gemm_kernel<<<(n_nodes + BM - 1) / BM, 256>>>(h, W_b, bias, out, n_nodes);
}

// round 5
// speedup vs baseline: 1.3705x; 1.3705x over previous
#include <cuda_runtime.h>

// ---------------------------------------------------------------------------
// FSRGraphConv:
//   acc[dst] += [h[src] | eftr[e]] (v4 vector REDs), cnt[dst] += 1
//   feat_mean = acc / max(cnt,1)
//   out = [h_dst | feat_mean] @ [W1t ; weight@W2^T] + (W_b + bias)
// Round 5: R2 scatter (proven) + register-double-buffered pipelined GEMM.
// ---------------------------------------------------------------------------

#define IN_F   128
#define E_F    32
#define FEAT   160
#define OUT_F  128
#define MAX_NODES 50000

__device__ __align__(16) float g_acc[(size_t)MAX_NODES * FEAT];   // 32 MB
__device__ float g_cnt[MAX_NODES];
__device__ __align__(16) float g_Wc[FEAT * OUT_F];    // weight @ W2^T (160x128)
__device__ __align__(16) float g_W1t[IN_F * OUT_F];   // W1t[k][o] = W_w[o][k]

// ---------------------------------------------------------------------------
__global__ void zero_kernel(int n_nodes) {
    size_t tid    = (size_t)blockIdx.x * blockDim.x + threadIdx.x;
    size_t stride = (size_t)gridDim.x * blockDim.x;
    size_t n4 = ((size_t)n_nodes * FEAT) / 4;
    float4* a4 = reinterpret_cast<float4*>(g_acc);
    float4 z = make_float4(0.f, 0.f, 0.f, 0.f);
    for (size_t i = tid; i < n4; i += stride) a4[i] = z;
    for (size_t i = tid; i < (size_t)n_nodes; i += stride) g_cnt[i] = 0.f;
}

__global__ void prep_wc_kernel(const float* __restrict__ weight,
                               const float* __restrict__ W_w) {
    __shared__ float wrow[OUT_F];
    int k = blockIdx.x;
    int o = threadIdx.x;
    wrow[o] = weight[k * OUT_F + o];
    __syncthreads();
    const float* wr = W_w + (size_t)o * (IN_F + OUT_F) + IN_F;
    float s = 0.f;
#pragma unroll 4
    for (int c = 0; c < OUT_F; c++) s = fmaf(wrow[c], wr[c], s);
    g_Wc[k * OUT_F + o] = s;
}

__global__ void prep_w1t_kernel(const float* __restrict__ W_w) {
    int idx = blockIdx.x * blockDim.x + threadIdx.x;
    if (idx < IN_F * OUT_F) {
        int k = idx >> 7;
        int o = idx & 127;
        g_W1t[idx] = W_w[(size_t)o * (IN_F + OUT_F) + k];
    }
}

// ---------------------------------------------------------------------------
__device__ __forceinline__ void red_v4(float* p, float4 v) {
    asm volatile("red.global.add.v4.f32 [%0], {%1, %2, %3, %4};"
                 :: "l"(p), "f"(v.x), "f"(v.y), "f"(v.z), "f"(v.w)
                 : "memory");
}

__global__ void scatter_kernel(const float* __restrict__ h,
                               const float* __restrict__ eftr,
                               const int*   __restrict__ src_idx,
                               const int*   __restrict__ dst_idx,
                               int n_edges) {
    int lane   = threadIdx.x & 31;
    int warp   = (blockIdx.x * blockDim.x + threadIdx.x) >> 5;
    int nwarps = (gridDim.x * blockDim.x) >> 5;

    for (int e = warp; e < n_edges; e += nwarps) {
        int s = src_idx[e];
        int d = dst_idx[e];
        float4 v = reinterpret_cast<const float4*>(h + (size_t)s * IN_F)[lane];
        float* arow = g_acc + (size_t)d * FEAT;
        red_v4(arow + lane * 4, v);
        if (lane < 8) {
            float4 ev = reinterpret_cast<const float4*>(eftr + (size_t)e * E_F)[lane];
            red_v4(arow + IN_F + lane * 4, ev);
        }
        if (lane == 0) atomicAdd(&g_cnt[d], 1.0f);
    }
}

// ---------------------------------------------------------------------------
// packed fp32x2 helpers
__device__ __forceinline__ unsigned long long ffma2(unsigned long long a,
                                                    unsigned long long b,
                                                    unsigned long long c) {
    unsigned long long d;
    asm("fma.rn.f32x2 %0, %1, %2, %3;" : "=l"(d) : "l"(a), "l"(b), "l"(c));
    return d;
}
__device__ __forceinline__ unsigned long long pack2(float lo, float hi) {
    unsigned long long d;
    asm("mov.b64 %0, {%1, %2};" : "=l"(d) : "f"(lo), "f"(hi));
    return d;
}
__device__ __forceinline__ float2 unpack2(unsigned long long v) {
    float lo, hi;
    asm("mov.b64 {%0, %1}, %2;" : "=f"(lo), "=f"(hi) : "l"(v));
    return make_float2(lo, hi);
}

// fused GEMM: out = [h_dst | feat_mean] @ [W1t; Wc] + (W_b + bias)
// BM=128, BN=128, BK=16, 18 chunks. 256 threads, 8x8/thread (f32x2).
// Register double-buffered: next tile's global loads overlap current compute.
#define BM 128
#define BN 128
#define BK 16
#define NKC 18

__global__ void gemm_kernel(const float* __restrict__ h,
                            const float* __restrict__ W_b,
                            const float* __restrict__ bias,
                            float* __restrict__ out,
                            int n_nodes) {
    __shared__ float Xs[BK][BM + 4];
    __shared__ __align__(16) float Ws[BK][BN];
    __shared__ float sden[BM];

    int m0 = blockIdx.x * BM;
    int t  = threadIdx.x;
    int tx = t & 15;
    int ty = t >> 4;

    if (t < BM) {
        int node = m0 + t;
        float c = (node < n_nodes) ? g_cnt[node] : 1.f;
        sden[t] = 1.f / fmaxf(c, 1.f);
    }
    __syncthreads();

    // per-thread load coordinates (constant across kc)
    int xm  = (t * 2)     >> 3;    // idx = t + i*256 -> m = idx>>2
    // we use i in {0,1}: idx0 = t, idx1 = t+256
    int m_0 = t >> 2,        k4_0 = t & 3;
    int m_1 = (t + 256) >> 2, k4_1 = (t + 256) & 3;
    int wk_0 = t >> 5,        wn_0 = t & 31;
    int wk_1 = (t + 256) >> 5, wn_1 = (t + 256) & 31;
    (void)xm;

    // ---- tile loader into registers ----
    float4 xr0, xr1, wr0, wr1;
    auto load_tile = [&](int kc) {
        int node0 = m0 + m_0, node1 = m0 + m_1;
        float4 v0 = make_float4(0.f,0.f,0.f,0.f);
        float4 v1 = make_float4(0.f,0.f,0.f,0.f);
        if (kc < 8) {
            if (node0 < n_nodes)
                v0 = *reinterpret_cast<const float4*>(h + (size_t)node0 * IN_F + kc * BK + k4_0 * 4);
            if (node1 < n_nodes)
                v1 = *reinterpret_cast<const float4*>(h + (size_t)node1 * IN_F + kc * BK + k4_1 * 4);
        } else {
            if (node0 < n_nodes) {
                v0 = *reinterpret_cast<const float4*>(g_acc + (size_t)node0 * FEAT + (kc - 8) * BK + k4_0 * 4);
                float dn = sden[m_0];
                v0.x *= dn; v0.y *= dn; v0.z *= dn; v0.w *= dn;
            }
            if (node1 < n_nodes) {
                v1 = *reinterpret_cast<const float4*>(g_acc + (size_t)node1 * FEAT + (kc - 8) * BK + k4_1 * 4);
                float dn = sden[m_1];
                v1.x *= dn; v1.y *= dn; v1.z *= dn; v1.w *= dn;
            }
        }
        xr0 = v0; xr1 = v1;
        const float* Wsrc = (kc < 8) ? (g_W1t + kc * BK * OUT_F)
                                     : (g_Wc + (kc - 8) * BK * OUT_F);
        wr0 = *reinterpret_cast<const float4*>(Wsrc + wk_0 * OUT_F + wn_0 * 4);
        wr1 = *reinterpret_cast<const float4*>(Wsrc + wk_1 * OUT_F + wn_1 * 4);
    };
    auto store_tile = [&]() {
        Xs[k4_0 * 4 + 0][m_0] = xr0.x;
        Xs[k4_0 * 4 + 1][m_0] = xr0.y;
        Xs[k4_0 * 4 + 2][m_0] = xr0.z;
        Xs[k4_0 * 4 + 3][m_0] = xr0.w;
        Xs[k4_1 * 4 + 0][m_1] = xr1.x;
        Xs[k4_1 * 4 + 1][m_1] = xr1.y;
        Xs[k4_1 * 4 + 2][m_1] = xr1.z;
        Xs[k4_1 * 4 + 3][m_1] = xr1.w;
        *reinterpret_cast<float4*>(&Ws[wk_0][wn_0 * 4]) = wr0;
        *reinterpret_cast<float4*>(&Ws[wk_1][wn_1 * 4]) = wr1;
    };

    unsigned long long acc2[8][4];
#pragma unroll
    for (int i = 0; i < 8; i++)
#pragma unroll
        for (int j = 0; j < 4; j++) acc2[i][j] = 0ull;

    load_tile(0);   // prologue

    for (int kc = 0; kc < NKC; kc++) {
        store_tile();
        __syncthreads();
        if (kc + 1 < NKC) load_tile(kc + 1);   // prefetch next while computing

#pragma unroll
        for (int kk = 0; kk < BK; kk++) {
            float4 x0 = *reinterpret_cast<const float4*>(&Xs[kk][ty * 8]);
            float4 x1 = *reinterpret_cast<const float4*>(&Xs[kk][ty * 8 + 4]);
            const unsigned long long* wrow =
                reinterpret_cast<const unsigned long long*>(&Ws[kk][tx * 8]);
            unsigned long long w01 = wrow[0];
            unsigned long long w23 = wrow[1];
            unsigned long long w45 = wrow[2];
            unsigned long long w67 = wrow[3];

            float xv[8] = {x0.x, x0.y, x0.z, x0.w, x1.x, x1.y, x1.z, x1.w};
#pragma unroll
            for (int i = 0; i < 8; i++) {
                unsigned long long xx = pack2(xv[i], xv[i]);
                acc2[i][0] = ffma2(xx, w01, acc2[i][0]);
                acc2[i][1] = ffma2(xx, w23, acc2[i][1]);
                acc2[i][2] = ffma2(xx, w45, acc2[i][2]);
                acc2[i][3] = ffma2(xx, w67, acc2[i][3]);
            }
        }
        __syncthreads();
    }

    float bv[8];
#pragma unroll
    for (int j = 0; j < 8; j++) {
        int o = tx * 8 + j;
        bv[j] = W_b[o] + bias[o];
    }
#pragma unroll
    for (int i = 0; i < 8; i++) {
        int node = m0 + ty * 8 + i;
        if (node < n_nodes) {
            float* orow = out + (size_t)node * OUT_F + tx * 8;
            float2 a01 = unpack2(acc2[i][0]);
            float2 a23 = unpack2(acc2[i][1]);
            float2 a45 = unpack2(acc2[i][2]);
            float2 a67 = unpack2(acc2[i][3]);
            float4 r0 = make_float4(a01.x + bv[0], a01.y + bv[1],
                                    a23.x + bv[2], a23.y + bv[3]);
            float4 r1 = make_float4(a45.x + bv[4], a45.y + bv[5],
                                    a67.x + bv[6], a67.y + bv[7]);
            *reinterpret_cast<float4*>(orow)     = r0;
            *reinterpret_cast<float4*>(orow + 4) = r1;
        }
    }
}

// ---------------------------------------------------------------------------
extern "C" void kernel_launch(void* const* d_in, const int* in_sizes, int n_in,
                              void* d_out, int out_size) {
    const float* h      = (const float*)d_in[0];
    const float* eftr   = (const float*)d_in[1];
    const float* weight = (const float*)d_in[2];
    const float* W_w    = (const float*)d_in[3];
    const float* W_b    = (const float*)d_in[4];
    const float* bias   = (const float*)d_in[5];
    const int*   src    = (const int*)d_in[6];
    const int*   dst    = (const int*)d_in[7];
    float* out = (float*)d_out;

    int n_nodes = in_sizes[0] / IN_F;
    int n_edges = in_sizes[7];

    zero_kernel<<<1024, 256>>>(n_nodes);
    prep_wc_kernel<<<FEAT, OUT_F>>>(weight, W_w);
    prep_w1t_kernel<<<(IN_F * OUT_F + 255) / 256, 256>>>(W_w);
    scatter_kernel<<<2048, 256>>>(h, eftr, src, dst, n_edges);
    gemm_kernel<<<(n_nodes + BM - 1) / BM, 256>>>(h, W_b, bias, out, n_nodes);
}

// round 6
// speedup vs baseline: 1.5353x; 1.1202x over previous
#include <cuda_runtime.h>

// ---------------------------------------------------------------------------
// FSRGraphConv, round 6: counting-sort (proper multi-block scan) ->
// warp-per-dst atomic-free aggregation -> pipelined fused GEMM.
//   out = [h_dst | feat_mean] @ [W1t ; weight@W2^T] + (W_b + bias)
// ---------------------------------------------------------------------------

#define IN_F   128
#define E_F    32
#define FEAT   160
#define OUT_F  128
#define MAX_NODES 50000
#define MAX_EDGES 800000

__device__ __align__(16) float g_acc[(size_t)MAX_NODES * FEAT];   // feat_mean
__device__ int  g_cnt[MAX_NODES];
__device__ int  g_off[MAX_NODES + 1];
__device__ int  g_cur[MAX_NODES];
__device__ int  g_bsum[256];
__device__ __align__(8) int2 g_pairs[MAX_EDGES];                  // (src, eid) by dst
__device__ __align__(16) float g_Wc[FEAT * OUT_F];
__device__ __align__(16) float g_W1t[IN_F * OUT_F];

// ---------------------------------------------------------------------------
__global__ void zero_cnt_kernel(int n_nodes) {
    int i = blockIdx.x * blockDim.x + threadIdx.x;
    if (i < n_nodes) g_cnt[i] = 0;
}

__global__ void hist_kernel(const int* __restrict__ dst_idx, int n_edges) {
    int i = blockIdx.x * blockDim.x + threadIdx.x;
    if (i < n_edges) atomicAdd(&g_cnt[dst_idx[i]], 1);
}

// ---- 3-kernel coalesced exclusive scan of g_cnt -> g_off / g_cur ----
__global__ void scanA_kernel(int n) {
    __shared__ int ss[256];
    int b = blockIdx.x, t = threadIdx.x, i = b * 256 + t;
    int c = (i < n) ? g_cnt[i] : 0;
    ss[t] = c; __syncthreads();
    for (int off = 1; off < 256; off <<= 1) {
        int v = (t >= off) ? ss[t - off] : 0;
        __syncthreads();
        ss[t] += v;
        __syncthreads();
    }
    if (i < n) g_off[i] = ss[t] - c;      // block-local exclusive
    if (t == 255) g_bsum[b] = ss[255];    // block total
}

__global__ void scanB_kernel(int nb, int n) {
    __shared__ int ss[256];
    int t = threadIdx.x;
    int v = (t < nb) ? g_bsum[t] : 0;
    ss[t] = v; __syncthreads();
    for (int off = 1; off < 256; off <<= 1) {
        int x = (t >= off) ? ss[t - off] : 0;
        __syncthreads();
        ss[t] += x;
        __syncthreads();
    }
    if (t < nb) g_bsum[t] = ss[t] - v;    // exclusive block bases
    if (t == 255) g_off[n] = ss[255];     // grand total
}

__global__ void scanC_kernel(int n) {
    int i = blockIdx.x * 256 + threadIdx.x;
    if (i < n) {
        int o = g_off[i] + g_bsum[blockIdx.x];
        g_off[i] = o;
        g_cur[i] = o;
    }
}

__global__ void bucket_kernel(const int* __restrict__ src_idx,
                              const int* __restrict__ dst_idx,
                              int n_edges) {
    int e = blockIdx.x * blockDim.x + threadIdx.x;
    if (e < n_edges) {
        int d = dst_idx[e];
        int pos = atomicAdd(&g_cur[d], 1);
        g_pairs[pos] = make_int2(src_idx[e], e);
    }
}

// one warp per dst; 2 edges/iter with dual accumulators (6 loads in flight)
__global__ void aggregate_kernel(const float* __restrict__ h,
                                 const float* __restrict__ eftr,
                                 int n_nodes) {
    int lane = threadIdx.x & 31;
    int w    = (blockIdx.x * blockDim.x + threadIdx.x) >> 5;
    if (w >= n_nodes) return;

    int start = g_off[w];
    int end   = g_off[w + 1];
    int n     = end - start;

    float4 a0 = make_float4(0.f, 0.f, 0.f, 0.f);
    float4 a1 = make_float4(0.f, 0.f, 0.f, 0.f);
    float  e0 = 0.f, e1 = 0.f;

    int j = start;
    for (; j + 1 < end; j += 2) {
        int2 c0 = g_pairs[j];
        int2 c1 = g_pairs[j + 1];
        float4 h0 = __ldg(reinterpret_cast<const float4*>(h + (size_t)c0.x * IN_F) + lane);
        float4 h1 = __ldg(reinterpret_cast<const float4*>(h + (size_t)c1.x * IN_F) + lane);
        float  v0 = __ldg(eftr + (size_t)c0.y * E_F + lane);
        float  v1 = __ldg(eftr + (size_t)c1.y * E_F + lane);
        a0.x += h0.x; a0.y += h0.y; a0.z += h0.z; a0.w += h0.w; e0 += v0;
        a1.x += h1.x; a1.y += h1.y; a1.z += h1.z; a1.w += h1.w; e1 += v1;
    }
    if (j < end) {
        int2 c0 = g_pairs[j];
        float4 h0 = __ldg(reinterpret_cast<const float4*>(h + (size_t)c0.x * IN_F) + lane);
        float  v0 = __ldg(eftr + (size_t)c0.y * E_F + lane);
        a0.x += h0.x; a0.y += h0.y; a0.z += h0.z; a0.w += h0.w; e0 += v0;
    }

    float inv = 1.f / (float)max(n, 1);
    float4 ah = make_float4((a0.x + a1.x) * inv, (a0.y + a1.y) * inv,
                            (a0.z + a1.z) * inv, (a0.w + a1.w) * inv);
    float  ae = (e0 + e1) * inv;

    float* arow = g_acc + (size_t)w * FEAT;
    reinterpret_cast<float4*>(arow)[lane] = ah;
    arow[IN_F + lane] = ae;
}

// ---------------------------------------------------------------------------
__global__ void prep_wc_kernel(const float* __restrict__ weight,
                               const float* __restrict__ W_w) {
    __shared__ float wrow[OUT_F];
    int k = blockIdx.x;
    int o = threadIdx.x;
    wrow[o] = weight[k * OUT_F + o];
    __syncthreads();
    const float* wr = W_w + (size_t)o * (IN_F + OUT_F) + IN_F;
    float s = 0.f;
#pragma unroll 4
    for (int c = 0; c < OUT_F; c++) s = fmaf(wrow[c], wr[c], s);
    g_Wc[k * OUT_F + o] = s;
}

__global__ void prep_w1t_kernel(const float* __restrict__ W_w) {
    int idx = blockIdx.x * blockDim.x + threadIdx.x;
    if (idx < IN_F * OUT_F) {
        int k = idx >> 7;
        int o = idx & 127;
        g_W1t[idx] = W_w[(size_t)o * (IN_F + OUT_F) + k];
    }
}

// ---------------------------------------------------------------------------
// packed fp32x2 helpers
__device__ __forceinline__ unsigned long long ffma2(unsigned long long a,
                                                    unsigned long long b,
                                                    unsigned long long c) {
    unsigned long long d;
    asm("fma.rn.f32x2 %0, %1, %2, %3;" : "=l"(d) : "l"(a), "l"(b), "l"(c));
    return d;
}
__device__ __forceinline__ unsigned long long pack2(float lo, float hi) {
    unsigned long long d;
    asm("mov.b64 %0, {%1, %2};" : "=l"(d) : "f"(lo), "f"(hi));
    return d;
}
__device__ __forceinline__ float2 unpack2(unsigned long long v) {
    float lo, hi;
    asm("mov.b64 {%0, %1}, %2;" : "=f"(lo), "=f"(hi) : "l"(v));
    return make_float2(lo, hi);
}

// fused GEMM (register double-buffered): out = [h_dst | feat_mean] @ [W1t; Wc] + b
#define BM 128
#define BN 128
#define BK 16
#define NKC 18

__global__ void gemm_kernel(const float* __restrict__ h,
                            const float* __restrict__ W_b,
                            const float* __restrict__ bias,
                            float* __restrict__ out,
                            int n_nodes) {
    __shared__ float Xs[BK][BM + 4];
    __shared__ __align__(16) float Ws[BK][BN];

    int m0 = blockIdx.x * BM;
    int t  = threadIdx.x;
    int tx = t & 15;
    int ty = t >> 4;

    int m_0 = t >> 2,          k4_0 = t & 3;
    int m_1 = (t + 256) >> 2,  k4_1 = (t + 256) & 3;
    int wk_0 = t >> 5,         wn_0 = t & 31;
    int wk_1 = (t + 256) >> 5, wn_1 = (t + 256) & 31;

    float4 xr0, xr1, wr0, wr1;
    auto load_tile = [&](int kc) {
        int node0 = m0 + m_0, node1 = m0 + m_1;
        float4 v0 = make_float4(0.f,0.f,0.f,0.f);
        float4 v1 = make_float4(0.f,0.f,0.f,0.f);
        if (kc < 8) {
            if (node0 < n_nodes)
                v0 = *reinterpret_cast<const float4*>(h + (size_t)node0 * IN_F + kc * BK + k4_0 * 4);
            if (node1 < n_nodes)
                v1 = *reinterpret_cast<const float4*>(h + (size_t)node1 * IN_F + kc * BK + k4_1 * 4);
        } else {
            if (node0 < n_nodes)
                v0 = *reinterpret_cast<const float4*>(g_acc + (size_t)node0 * FEAT + (kc - 8) * BK + k4_0 * 4);
            if (node1 < n_nodes)
                v1 = *reinterpret_cast<const float4*>(g_acc + (size_t)node1 * FEAT + (kc - 8) * BK + k4_1 * 4);
        }
        xr0 = v0; xr1 = v1;
        const float* Wsrc = (kc < 8) ? (g_W1t + kc * BK * OUT_F)
                                     : (g_Wc + (kc - 8) * BK * OUT_F);
        wr0 = *reinterpret_cast<const float4*>(Wsrc + wk_0 * OUT_F + wn_0 * 4);
        wr1 = *reinterpret_cast<const float4*>(Wsrc + wk_1 * OUT_F + wn_1 * 4);
    };
    auto store_tile = [&]() {
        Xs[k4_0 * 4 + 0][m_0] = xr0.x;
        Xs[k4_0 * 4 + 1][m_0] = xr0.y;
        Xs[k4_0 * 4 + 2][m_0] = xr0.z;
        Xs[k4_0 * 4 + 3][m_0] = xr0.w;
        Xs[k4_1 * 4 + 0][m_1] = xr1.x;
        Xs[k4_1 * 4 + 1][m_1] = xr1.y;
        Xs[k4_1 * 4 + 2][m_1] = xr1.z;
        Xs[k4_1 * 4 + 3][m_1] = xr1.w;
        *reinterpret_cast<float4*>(&Ws[wk_0][wn_0 * 4]) = wr0;
        *reinterpret_cast<float4*>(&Ws[wk_1][wn_1 * 4]) = wr1;
    };

    unsigned long long acc2[8][4];
#pragma unroll
    for (int i = 0; i < 8; i++)
#pragma unroll
        for (int j = 0; j < 4; j++) acc2[i][j] = 0ull;

    load_tile(0);

    for (int kc = 0; kc < NKC; kc++) {
        store_tile();
        __syncthreads();
        if (kc + 1 < NKC) load_tile(kc + 1);

#pragma unroll
        for (int kk = 0; kk < BK; kk++) {
            float4 x0 = *reinterpret_cast<const float4*>(&Xs[kk][ty * 8]);
            float4 x1 = *reinterpret_cast<const float4*>(&Xs[kk][ty * 8 + 4]);
            const unsigned long long* wrow =
                reinterpret_cast<const unsigned long long*>(&Ws[kk][tx * 8]);
            unsigned long long w01 = wrow[0];
            unsigned long long w23 = wrow[1];
            unsigned long long w45 = wrow[2];
            unsigned long long w67 = wrow[3];

            float xv[8] = {x0.x, x0.y, x0.z, x0.w, x1.x, x1.y, x1.z, x1.w};
#pragma unroll
            for (int i = 0; i < 8; i++) {
                unsigned long long xx = pack2(xv[i], xv[i]);
                acc2[i][0] = ffma2(xx, w01, acc2[i][0]);
                acc2[i][1] = ffma2(xx, w23, acc2[i][1]);
                acc2[i][2] = ffma2(xx, w45, acc2[i][2]);
                acc2[i][3] = ffma2(xx, w67, acc2[i][3]);
            }
        }
        __syncthreads();
    }

    float bv[8];
#pragma unroll
    for (int j = 0; j < 8; j++) {
        int o = tx * 8 + j;
        bv[j] = W_b[o] + bias[o];
    }
#pragma unroll
    for (int i = 0; i < 8; i++) {
        int node = m0 + ty * 8 + i;
        if (node < n_nodes) {
            float* orow = out + (size_t)node * OUT_F + tx * 8;
            float2 a01 = unpack2(acc2[i][0]);
            float2 a23 = unpack2(acc2[i][1]);
            float2 a45 = unpack2(acc2[i][2]);
            float2 a67 = unpack2(acc2[i][3]);
            float4 r0 = make_float4(a01.x + bv[0], a01.y + bv[1],
                                    a23.x + bv[2], a23.y + bv[3]);
            float4 r1 = make_float4(a45.x + bv[4], a45.y + bv[5],
                                    a67.x + bv[6], a67.y + bv[7]);
            *reinterpret_cast<float4*>(orow)     = r0;
            *reinterpret_cast<float4*>(orow + 4) = r1;
        }
    }
}

// ---------------------------------------------------------------------------
extern "C" void kernel_launch(void* const* d_in, const int* in_sizes, int n_in,
                              void* d_out, int out_size) {
    const float* h      = (const float*)d_in[0];
    const float* eftr   = (const float*)d_in[1];
    const float* weight = (const float*)d_in[2];
    const float* W_w    = (const float*)d_in[3];
    const float* W_b    = (const float*)d_in[4];
    const float* bias   = (const float*)d_in[5];
    const int*   src    = (const int*)d_in[6];
    const int*   dst    = (const int*)d_in[7];
    float* out = (float*)d_out;

    int n_nodes = in_sizes[0] / IN_F;
    int n_edges = in_sizes[7];
    int nb = (n_nodes + 255) / 256;   // 196 <= 256

    zero_cnt_kernel<<<nb, 256>>>(n_nodes);
    prep_wc_kernel<<<FEAT, OUT_F>>>(weight, W_w);
    prep_w1t_kernel<<<(IN_F * OUT_F + 255) / 256, 256>>>(W_w);
    hist_kernel<<<(n_edges + 255) / 256, 256>>>(dst, n_edges);
    scanA_kernel<<<nb, 256>>>(n_nodes);
    scanB_kernel<<<1, 256>>>(nb, n_nodes);
    scanC_kernel<<<nb, 256>>>(n_nodes);
    bucket_kernel<<<(n_edges + 255) / 256, 256>>>(src, dst, n_edges);
    aggregate_kernel<<<(n_nodes * 32 + 255) / 256, 256>>>(h, eftr, n_nodes);
    gemm_kernel<<<(n_nodes + BM - 1) / BM, 256>>>(h, W_b, bias, out, n_nodes);
}